// round 1
// baseline (speedup 1.0000x reference)
#include <cuda_runtime.h>

// FuzzyNeuron: out[n] = sum_r z[n,r]*w[n,r] / (sum_r w[n,r] + 1e-13)
//   z[n,r]    = dot(x[n], rho[r,:A]) + rho[r,A]
//   logw[n,r] = -sum_a (x[n,a]-mu[r,a])^2 / (2 sigma[r,a]^2)
//             =  sum_a (q[r,a]*x^2 + b[r,a]*x) + f[r]
//     with q = -1/(2s^2), b = mu/s^2, f = -sum_a mu^2/(2s^2)
//
// Strategy: FMA-pipe bound -> use packed fp32 fma.rn.f32x2 (2 rows per
// register pair), 4 rows per thread (2 packed chains) to amortize the
// shared-memory coefficient stream. Coefficients pre-duplicated in smem
// so LDS.128/LDS.64 yield ready-to-use f32x2 operands (broadcast, N=1).

#define N_TOT 131072
#define A_DIM 16
#define R_RULES 64
#define BLOCK 128

typedef unsigned long long u64;

__device__ __forceinline__ u64 pack2(float lo, float hi) {
    u64 r;
    asm("mov.b64 %0, {%1, %2};" : "=l"(r) : "f"(lo), "f"(hi));
    return r;
}
__device__ __forceinline__ void unpack2(float& lo, float& hi, u64 v) {
    asm("mov.b64 {%0, %1}, %2;" : "=f"(lo), "=f"(hi) : "l"(v));
}
__device__ __forceinline__ u64 fma2(u64 a, u64 b, u64 c) {
    u64 d;
    asm("fma.rn.f32x2 %0, %1, %2, %3;" : "=l"(d) : "l"(a), "l"(b), "l"(c));
    return d;
}
__device__ __forceinline__ u64 add2(u64 a, u64 b) {
    u64 d;
    asm("add.rn.f32x2 %0, %1, %2;" : "=l"(d) : "l"(a), "l"(b));
    return d;
}

__global__ void __launch_bounds__(BLOCK)
fuzzy_neuron_kernel(const float* __restrict__ x,
                    const float* __restrict__ mu,
                    const float* __restrict__ sigma,
                    const float* __restrict__ rho,
                    float* __restrict__ out,
                    int n_rows) {
    // Coefficients, pre-duplicated into both halves of 64-bit pairs so a
    // single LDS.128 / LDS.64 gives f32x2-ready operands.
    __shared__ ulonglong2 sQB[R_RULES * A_DIM];   // {q,q},{b,b}   16 KB
    __shared__ u64        sRho[R_RULES * A_DIM];  // {rho,rho}      8 KB
    __shared__ ulonglong2 sBF[R_RULES];           // {bias,bias},{f,f} 1 KB

    const int tid = threadIdx.x;

    // ---- per-block coefficient setup (broadcast-read, L2-resident) ----
    for (int idx = tid; idx < R_RULES * A_DIM; idx += BLOCK) {
        int r = idx >> 4;
        int a = idx & (A_DIM - 1);
        float m = mu[idx];
        float s = sigma[idx];
        float c = 1.0f / (2.0f * s * s);
        float q = -c;
        float b = 2.0f * c * m;
        float rh = rho[r * (A_DIM + 1) + a];
        sQB[idx] = make_ulonglong2(pack2(q, q), pack2(b, b));
        sRho[idx] = pack2(rh, rh);
    }
    for (int r = tid; r < R_RULES; r += BLOCK) {
        float bias = rho[r * (A_DIM + 1) + A_DIM];
        float f = 0.0f;
        for (int a = 0; a < A_DIM; a++) {
            float m = mu[r * A_DIM + a];
            float s = sigma[r * A_DIM + a];
            f -= (m * m) / (2.0f * s * s);
        }
        sBF[r] = make_ulonglong2(pack2(bias, bias), pack2(f, f));
    }
    __syncthreads();

    // ---- 4 rows per thread: rows gid, gid+Q, gid+2Q, gid+3Q ----
    const int quarter = n_rows >> 2;
    const int gid = blockIdx.x * BLOCK + tid;
    if (gid >= quarter) return;
    const int r0 = gid;
    const int r1 = gid + quarter;
    const int r2 = gid + 2 * quarter;
    const int r3 = gid + 3 * quarter;

    // Load x rows as float4 and pack pairwise: chain0 = (r0,r1), chain1 = (r2,r3)
    const float4* x4 = reinterpret_cast<const float4*>(x);
    u64 xp0[A_DIM], xp1[A_DIM];
#pragma unroll
    for (int j = 0; j < 4; j++) {
        float4 a0 = x4[r0 * 4 + j];
        float4 a1 = x4[r1 * 4 + j];
        float4 a2 = x4[r2 * 4 + j];
        float4 a3 = x4[r3 * 4 + j];
        xp0[4 * j + 0] = pack2(a0.x, a1.x);
        xp0[4 * j + 1] = pack2(a0.y, a1.y);
        xp0[4 * j + 2] = pack2(a0.z, a1.z);
        xp0[4 * j + 3] = pack2(a0.w, a1.w);
        xp1[4 * j + 0] = pack2(a2.x, a3.x);
        xp1[4 * j + 1] = pack2(a2.y, a3.y);
        xp1[4 * j + 2] = pack2(a2.z, a3.z);
        xp1[4 * j + 3] = pack2(a2.w, a3.w);
    }

    u64 num0 = 0ULL, den0 = 0ULL, num1 = 0ULL, den1 = 0ULL;

    const ulonglong2* qb = sQB;
    const u64* rp = sRho;

    // Rule loop kept rolled (body ~1.3 KB, fits L0 I$); A-loop fully unrolled.
    for (int r = 0; r < R_RULES; r++) {
        ulonglong2 bf = sBF[r];
        u64 z0 = bf.x, z1 = bf.x;
        u64 l0 = bf.y, l1 = bf.y;
#pragma unroll
        for (int a = 0; a < A_DIM; a++) {
            ulonglong2 cqb = qb[a];   // {q,q},{b,b}  LDS.128 broadcast
            u64 rr = rp[a];           // {rho,rho}    LDS.64  broadcast
            u64 t0 = fma2(xp0[a], cqb.x, cqb.y);   // q*x + b
            u64 t1 = fma2(xp1[a], cqb.x, cqb.y);
            l0 = fma2(xp0[a], t0, l0);             // += q*x^2 + b*x
            l1 = fma2(xp1[a], t1, l1);
            z0 = fma2(xp0[a], rr, z0);             // += rho*x
            z1 = fma2(xp1[a], rr, z1);
        }
        qb += A_DIM;
        rp += A_DIM;

        float la, lb, lc, ld;
        unpack2(la, lb, l0);
        unpack2(lc, ld, l1);
        float wa = __expf(la);
        float wb = __expf(lb);
        float wc = __expf(lc);
        float wd = __expf(ld);
        u64 w0 = pack2(wa, wb);
        u64 w1 = pack2(wc, wd);
        num0 = fma2(z0, w0, num0);
        num1 = fma2(z1, w1, num1);
        den0 = add2(den0, w0);
        den1 = add2(den1, w1);
    }

    float n00, n01, n10, n11, d00, d01, d10, d11;
    unpack2(n00, n01, num0);
    unpack2(n10, n11, num1);
    unpack2(d00, d01, den0);
    unpack2(d10, d11, den1);

    out[r0] = n00 / (d00 + 1e-13f);
    out[r1] = n01 / (d01 + 1e-13f);
    out[r2] = n10 / (d10 + 1e-13f);
    out[r3] = n11 / (d11 + 1e-13f);
}

extern "C" void kernel_launch(void* const* d_in, const int* in_sizes, int n_in,
                              void* d_out, int out_size) {
    const float* x = (const float*)d_in[0];      // [N, 16]
    const float* mu = (const float*)d_in[1];     // [64, 16]
    const float* sigma = (const float*)d_in[2];  // [64, 16]
    const float* rho = (const float*)d_in[3];    // [64, 17]
    float* out = (float*)d_out;                  // [N]

    const int n_rows = in_sizes[0] / A_DIM;      // 131072
    const int threads = n_rows / 4;
    const int blocks = (threads + BLOCK - 1) / BLOCK;

    fuzzy_neuron_kernel<<<blocks, BLOCK>>>(x, mu, sigma, rho, out, n_rows);
}